// round 6
// baseline (speedup 1.0000x reference)
#include <cuda_runtime.h>
#include <cuda_bf16.h>
#include <cstdint>
#include <math.h>

#define T_TOK 2048
#define H_DIM 1024
#define NE    32
#define IDIM  512
#define K_TOP 6
#define ISH   1024
#define CAP   2048
#define NPAIR (T_TOK*K_TOP)   // 12288

typedef __nv_bfloat16 bf16;

// ---------------- scratch (static device globals; no runtime alloc) ----------
__device__ int   g_counts[NE];
__device__ int   g_offsets[NE];
__device__ int   g_bucket[NE*CAP];
__device__ int   g_topidx[NPAIR];
__device__ float g_topw[NPAIR];
__device__ int   g_slot[NPAIR];

// bf16 hi/lo planes
__device__ bf16  g_x_hi   [(size_t)T_TOK*H_DIM],   g_x_lo   [(size_t)T_TOK*H_DIM];
__device__ bf16  g_sguw_hi[(size_t)2*ISH*H_DIM],   g_sguw_lo[(size_t)2*ISH*H_DIM];
__device__ bf16  g_sdw_hi [(size_t)H_DIM*ISH],     g_sdw_lo [(size_t)H_DIM*ISH];
__device__ bf16  g_gup_hi [(size_t)NE*2*IDIM*H_DIM], g_gup_lo[(size_t)NE*2*IDIM*H_DIM];
__device__ bf16  g_dwn_hi [(size_t)NE*H_DIM*IDIM], g_dwn_lo [(size_t)NE*H_DIM*IDIM];
__device__ bf16  g_smid_hi[(size_t)T_TOK*ISH],     g_smid_lo[(size_t)T_TOK*ISH];
__device__ bf16  g_hmid_hi[(size_t)NPAIR*IDIM],    g_hmid_lo[(size_t)NPAIR*IDIM];
// fp32 GEMM outputs
__device__ float g_sgu[(size_t)T_TOK*2*ISH];
__device__ float g_gu [(size_t)NPAIR*2*IDIM];
__device__ float g_y  [(size_t)NPAIR*H_DIM];

__device__ __forceinline__ float silu_f(float v){ return v / (1.f + __expf(-v)); }

__device__ __forceinline__ uint32_t smem_u32(const void* p){
    uint32_t a;
    asm("{ .reg .u64 t; cvta.to.shared.u64 t, %1; cvt.u32.u64 %0, t; }"
        : "=r"(a) : "l"(p));
    return a;
}

__device__ __forceinline__ void cpa16(uint32_t dst, const void* src, bool valid){
    asm volatile("cp.async.cg.shared.global [%0], [%1], 16, %2;"
                 :: "r"(dst), "l"(src), "r"(valid ? 16u : 0u) : "memory");
}
#define CPA_COMMIT() asm volatile("cp.async.commit_group;" ::: "memory")
#define CPA_WAIT1()  asm volatile("cp.async.wait_group 1;" ::: "memory")
#define CPA_WAIT0()  asm volatile("cp.async.wait_group 0;" ::: "memory")

__device__ __forceinline__ void mma16(float* c, const uint32_t* a, const uint32_t* b){
    asm volatile("mma.sync.aligned.m16n8k16.row.col.f32.bf16.bf16.f32 "
                 "{%0,%1,%2,%3}, {%4,%5,%6,%7}, {%8,%9}, {%0,%1,%2,%3};"
                 : "+f"(c[0]), "+f"(c[1]), "+f"(c[2]), "+f"(c[3])
                 : "r"(a[0]), "r"(a[1]), "r"(a[2]), "r"(a[3]),
                   "r"(b[0]), "r"(b[1]));
}

// split float2 -> bf16x2 hi (low half = first elem) + bf16x2 lo
__device__ __forceinline__ void split2(float2 f, uint32_t& hi, uint32_t& lo){
    asm("cvt.rn.bf16x2.f32 %0, %1, %2;" : "=r"(hi) : "f"(f.y), "f"(f.x));
    float h0 = __uint_as_float(hi << 16);
    float h1 = __uint_as_float(hi & 0xFFFF0000u);
    float l0 = f.x - h0, l1 = f.y - h1;
    asm("cvt.rn.bf16x2.f32 %0, %1, %2;" : "=r"(lo) : "f"(l1), "f"(l0));
}

// ======================= bf16 hi/lo 3-term GEMM ==============================
// C[m,n] = sum_k A[m,k]*B[n,k], operands pre-split into bf16 hi/lo planes.
// CTA tile 128x128, BK=32, 256 threads = 8 warps (2m x 4n), warp tile 64x32.
// smem per buffer: Ahi 8K | Alo 8K | Bhi 8K | Blo 8K (32KB), double-buffered.
// Plane rows: 32 bf16 = 64B = 4x16B units; swizzle unit ^= (row>>1)&3
// => all fragment LDS.32 conflict-free; cp.async dst 16B-aligned.
// MODE 0: dense; MODE 1: grouped gather via g_bucket; MODE 2: grouped compact.

#define GEMM_SMEM 65536

// swizzled bf16x2 (pair) load: pair index p in [0,16), row in [0,128)
__device__ __forceinline__ uint32_t ldp(const char* plane, int row, int pair){
    return *(const uint32_t*)(plane + row*64 + 4*(pair ^ (((row >> 1) & 3) << 2)));
}

template<int MODE>
__global__ __launch_bounds__(256, 2)
void gemm_bf(const bf16* __restrict__ Ahi, const bf16* __restrict__ Alo,
             const bf16* __restrict__ Bhi, const bf16* __restrict__ Blo,
             float* __restrict__ C, int M, int N, int K)
{
    int e = 0, cnt = M, off = 0;
    size_t woff = 0;
    if (MODE){
        e = blockIdx.z;
        cnt = g_counts[e];
        if ((int)blockIdx.y * 128 >= cnt) return;
        off = g_offsets[e];
        woff = (size_t)e * N * K;
    }
    const int m0 = blockIdx.y * 128, n0 = blockIdx.x * 128;

    extern __shared__ char sm[];
    const uint32_t sb = smem_u32(sm);

    const int tid = threadIdx.x, warp = tid >> 5, lane = tid & 31;
    const int wm = (warp >> 2) * 64, wn = (warp & 3) * 32;
    const int r4 = lane >> 2, c2 = lane & 3;

    // global load setup: each thread owns 1 row, 2 consecutive 16B units/plane
    const int lr = tid >> 1, uu = (tid & 1) * 2;
    const int m = m0 + lr;
    bool avalid; size_t garow;
    if (MODE == 0){ avalid = true; garow = (size_t)m; }
    else if (MODE == 1){ avalid = m < cnt; garow = avalid ? (size_t)g_bucket[e*CAP + m] : 0; }
    else { avalid = m < cnt; garow = (size_t)(off + (avalid ? m : 0)); }

    const bf16* a_hi = Ahi + garow * (size_t)K + uu*8;
    const bf16* a_lo = Alo + garow * (size_t)K + uu*8;
    const bf16* b_hi = Bhi + woff + (size_t)(n0 + lr) * K + uu*8;
    const bf16* b_lo = Blo + woff + (size_t)(n0 + lr) * K + uu*8;

    const uint32_t sw  = (uint32_t)((lr >> 1) & 3);
    const uint32_t d0  = (uint32_t)(lr*64 + 16*((uu)     ^ sw));
    const uint32_t d1  = (uint32_t)(lr*64 + 16*((uu + 1) ^ sw));

    float acc[4][4][4];
    #pragma unroll
    for (int a = 0; a < 4; a++)
    #pragma unroll
    for (int b = 0; b < 4; b++)
    #pragma unroll
    for (int q = 0; q < 4; q++) acc[a][b][q] = 0.f;

    const int nk = K >> 5;

    // prologue: chunk 0 -> buffer 0
    {
        cpa16(sb + d0,         a_hi, avalid); cpa16(sb + d1,         a_hi + 8, avalid);
        cpa16(sb + 8192 + d0,  a_lo, avalid); cpa16(sb + 8192 + d1,  a_lo + 8, avalid);
        cpa16(sb + 16384 + d0, b_hi, true);   cpa16(sb + 16384 + d1, b_hi + 8, true);
        cpa16(sb + 24576 + d0, b_lo, true);   cpa16(sb + 24576 + d1, b_lo + 8, true);
    }
    CPA_COMMIT();

    for (int ch = 0; ch < nk; ch++){
        const int b = ch & 1;
        if (ch + 1 < nk){
            const uint32_t bo = sb + (uint32_t)(((ch + 1) & 1) * 32768);
            const int ko = (ch + 1) << 5;
            cpa16(bo + d0,         a_hi + ko, avalid); cpa16(bo + d1,         a_hi + ko + 8, avalid);
            cpa16(bo + 8192 + d0,  a_lo + ko, avalid); cpa16(bo + 8192 + d1,  a_lo + ko + 8, avalid);
            cpa16(bo + 16384 + d0, b_hi + ko, true);   cpa16(bo + 16384 + d1, b_hi + ko + 8, true);
            cpa16(bo + 24576 + d0, b_lo + ko, true);   cpa16(bo + 24576 + d1, b_lo + ko + 8, true);
            CPA_COMMIT();
            CPA_WAIT1();
        } else {
            CPA_WAIT0();
        }
        __syncthreads();

        const char* base = sm + b * 32768;
        const char* pAh = base;
        const char* pAl = base + 8192;
        const char* pBh = base + 16384;
        const char* pBl = base + 24576;

        #pragma unroll
        for (int ks = 0; ks < 2; ks++){
            const int pb = ks*8 + c2;
            uint32_t bh[4][2], bl[4][2];
            #pragma unroll
            for (int nf = 0; nf < 4; nf++){
                const int nr = wn + nf*8 + r4;
                bh[nf][0] = ldp(pBh, nr, pb); bh[nf][1] = ldp(pBh, nr, pb + 4);
                bl[nf][0] = ldp(pBl, nr, pb); bl[nf][1] = ldp(pBl, nr, pb + 4);
            }
            #pragma unroll
            for (int mf = 0; mf < 4; mf++){
                const int mr = wm + mf*16 + r4;
                uint32_t ah[4], al[4];
                ah[0] = ldp(pAh, mr,     pb); ah[1] = ldp(pAh, mr + 8, pb);
                ah[2] = ldp(pAh, mr,     pb + 4); ah[3] = ldp(pAh, mr + 8, pb + 4);
                al[0] = ldp(pAl, mr,     pb); al[1] = ldp(pAl, mr + 8, pb);
                al[2] = ldp(pAl, mr,     pb + 4); al[3] = ldp(pAl, mr + 8, pb + 4);
                #pragma unroll
                for (int nf = 0; nf < 4; nf++){
                    mma16(acc[mf][nf], ah, bh[nf]);
                    mma16(acc[mf][nf], ah, bl[nf]);
                    mma16(acc[mf][nf], al, bh[nf]);
                }
            }
        }
        __syncthreads();
    }

    // epilogue
    #pragma unroll
    for (int mf = 0; mf < 4; mf++){
        const int rl = wm + mf*16 + r4;
        #pragma unroll
        for (int half = 0; half < 2; half++){
            const int rloc = rl + half*8;
            bool valid; size_t crow;
            if (MODE == 0){ valid = true; crow = (size_t)(m0 + rloc); }
            else { valid = (m0 + rloc) < cnt; crow = (size_t)(off + m0 + rloc); }
            if (valid){
                float* cp = C + crow * N + n0 + wn + c2*2;
                #pragma unroll
                for (int nf = 0; nf < 4; nf++){
                    float2 v;
                    v.x = acc[mf][nf][half*2 + 0];
                    v.y = acc[mf][nf][half*2 + 1];
                    *(float2*)(cp + nf*8) = v;
                }
            }
        }
    }
}

// ---------------- split pass: fp32 -> bf16 hi/lo planes ----------------------
__global__ void split_kernel(const float* __restrict__ src,
                             bf16* __restrict__ hi, bf16* __restrict__ lo, int n4)
{
    int i = blockIdx.x * blockDim.x + threadIdx.x;
    if (i < n4){
        float4 v = ((const float4*)src)[i];
        uint32_t h01, l01, h23, l23;
        split2(make_float2(v.x, v.y), h01, l01);
        split2(make_float2(v.z, v.w), h23, l23);
        ((uint2*)hi)[i] = make_uint2(h01, h23);
        ((uint2*)lo)[i] = make_uint2(l01, l23);
    }
}

// ---------------- router: softmax + bias + top-6 + bucketing ----------------
__global__ void zero_counts_kernel(){
    if (threadIdx.x < NE) g_counts[threadIdx.x] = 0;
}

__global__ void router_kernel(const float* __restrict__ x,
                              const float* __restrict__ rw,
                              const float* __restrict__ bias)
{
    __shared__ float sx[H_DIM];
    __shared__ float slog[NE];
    const int t = blockIdx.x;
    const float* xr = x + (size_t)t * H_DIM;
    for (int i = threadIdx.x; i < H_DIM; i += blockDim.x) sx[i] = xr[i];
    __syncthreads();

    const int warp = threadIdx.x >> 5, lane = threadIdx.x & 31;
    for (int e = warp*8; e < warp*8 + 8; e++){
        const float* w = rw + (size_t)e * H_DIM;
        float s = 0.f;
        for (int h = lane; h < H_DIM; h += 32) s += sx[h] * w[h];
        #pragma unroll
        for (int o = 16; o; o >>= 1) s += __shfl_xor_sync(0xffffffffu, s, o);
        if (lane == 0) slog[e] = s;
    }
    __syncthreads();

    if (threadIdx.x == 0){
        float mx = -1e30f;
        for (int e = 0; e < NE; e++) mx = fmaxf(mx, slog[e]);
        float p[NE]; float sum = 0.f;
        for (int e = 0; e < NE; e++){ p[e] = expf(slog[e] - mx); sum += p[e]; }
        float inv = 1.f / sum;
        float corr[NE];
        for (int e = 0; e < NE; e++){ p[e] *= inv; corr[e] = p[e] + bias[e]; }

        int idx[K_TOP]; bool used[NE];
        for (int e = 0; e < NE; e++) used[e] = false;
        for (int k = 0; k < K_TOP; k++){
            int best = -1; float bv = -1e30f;
            for (int e = 0; e < NE; e++)
                if (!used[e] && corr[e] > bv){ bv = corr[e]; best = e; }
            used[best] = true; idx[k] = best;
        }
        float wsum = 0.f;
        for (int k = 0; k < K_TOP; k++) wsum += p[idx[k]];
        wsum = fmaxf(wsum, 1e-12f);
        for (int k = 0; k < K_TOP; k++){
            int e = idx[k];
            float wn = p[e] / wsum;
            int slot = atomicAdd(&g_counts[e], 1);
            g_bucket[e*CAP + slot] = t;
            g_topidx[t*K_TOP + k] = e;
            g_topw [t*K_TOP + k] = wn;
            g_slot [t*K_TOP + k] = slot;
        }
    }
}

__global__ void scan_kernel(){
    if (threadIdx.x == 0){
        int s = 0;
        for (int e = 0; e < NE; e++){ g_offsets[e] = s; s += g_counts[e]; }
    }
}

// ---------------- elementwise (fused split outputs) --------------------------
__global__ void silu_mul_shared_kernel(){
    // g_sgu: [T, 2048] (gate | up); out: g_smid planes [T, 1024], 2 elems/thread
    int i = blockIdx.x * blockDim.x + threadIdx.x;   // over T*ISH/2
    if (i < T_TOK*ISH/2){
        int t = i / (ISH/2), c = (i % (ISH/2)) * 2;
        const float* row = g_sgu + (size_t)t * 2 * ISH;
        float2 r;
        r.x = silu_f(row[c])     * row[ISH + c];
        r.y = silu_f(row[c + 1]) * row[ISH + c + 1];
        uint32_t h, l;
        split2(r, h, l);
        ((uint32_t*)g_smid_hi)[(size_t)t*(ISH/2) + (c>>1)] = h;
        ((uint32_t*)g_smid_lo)[(size_t)t*(ISH/2) + (c>>1)] = l;
    }
}

__global__ void silu_mul_grouped_kernel(){
    // g_gu: [NPAIR, 1024] (gate | up); out: g_hmid planes [NPAIR, 512]
    int i = blockIdx.x * blockDim.x + threadIdx.x;   // over NPAIR*IDIM/2
    if (i < NPAIR*IDIM/2){
        int p = i / (IDIM/2), c = (i % (IDIM/2)) * 2;
        const float* row = g_gu + (size_t)p * 2 * IDIM;
        float2 r;
        r.x = silu_f(row[c])     * row[IDIM + c];
        r.y = silu_f(row[c + 1]) * row[IDIM + c + 1];
        uint32_t h, l;
        split2(r, h, l);
        ((uint32_t*)g_hmid_hi)[(size_t)p*(IDIM/2) + (c>>1)] = h;
        ((uint32_t*)g_hmid_lo)[(size_t)p*(IDIM/2) + (c>>1)] = l;
    }
}

// ---------------- combine: deterministic per-token sum of 6 expert rows ------
__global__ void combine_kernel(float* __restrict__ out){
    const int t = blockIdx.x;
    const int h = blockIdx.y * 256 + threadIdx.x;
    float acc = 0.f;
    #pragma unroll
    for (int k = 0; k < K_TOP; k++){
        int e    = g_topidx[t*K_TOP + k];
        float w  = g_topw [t*K_TOP + k];
        int row  = g_offsets[e] + g_slot[t*K_TOP + k];
        acc += w * g_y[(size_t)row * H_DIM + h];
    }
    out[(size_t)t * H_DIM + h] += acc;   // out already holds shared_out
}

// ---------------- launch ------------------------------------------------------
static void* sym(const void* s){ void* p; cudaGetSymbolAddress(&p, s); return p; }

extern "C" void kernel_launch(void* const* d_in, const int* in_sizes, int n_in,
                              void* d_out, int out_size)
{
    const float* x    = (const float*)d_in[0];
    const float* rw   = (const float*)d_in[1];
    const float* bias = (const float*)d_in[2];
    const float* gup  = (const float*)d_in[3];
    const float* dwn  = (const float*)d_in[4];
    const float* sgw  = (const float*)d_in[5];
    const float* suw  = (const float*)d_in[6];
    const float* sdw  = (const float*)d_in[7];
    float* out = (float*)d_out;

    bf16 *xh = (bf16*)sym(g_x_hi), *xl = (bf16*)sym(g_x_lo);
    bf16 *sguwh = (bf16*)sym(g_sguw_hi), *sguwl = (bf16*)sym(g_sguw_lo);
    bf16 *sdwh = (bf16*)sym(g_sdw_hi), *sdwl = (bf16*)sym(g_sdw_lo);
    bf16 *guph = (bf16*)sym(g_gup_hi), *gupl = (bf16*)sym(g_gup_lo);
    bf16 *dwnh = (bf16*)sym(g_dwn_hi), *dwnl = (bf16*)sym(g_dwn_lo);
    bf16 *smh = (bf16*)sym(g_smid_hi), *sml = (bf16*)sym(g_smid_lo);
    bf16 *hmh = (bf16*)sym(g_hmid_hi), *hml = (bf16*)sym(g_hmid_lo);
    float *sgu = (float*)sym(g_sgu), *gu = (float*)sym(g_gu), *y = (float*)sym(g_y);

    cudaFuncSetAttribute(gemm_bf<0>, cudaFuncAttributeMaxDynamicSharedMemorySize, GEMM_SMEM);
    cudaFuncSetAttribute(gemm_bf<1>, cudaFuncAttributeMaxDynamicSharedMemorySize, GEMM_SMEM);
    cudaFuncSetAttribute(gemm_bf<2>, cudaFuncAttributeMaxDynamicSharedMemorySize, GEMM_SMEM);

    // routing
    zero_counts_kernel<<<1, 32>>>();
    router_kernel<<<T_TOK, 128>>>(x, rw, bias);
    scan_kernel<<<1, 32>>>();

    // operand splits (fp32 -> bf16 hi/lo planes)
    {
        int n4;
        n4 = T_TOK*H_DIM/4;
        split_kernel<<<(n4 + 255)/256, 256>>>(x, xh, xl, n4);
        n4 = ISH*H_DIM/4;
        split_kernel<<<(n4 + 255)/256, 256>>>(sgw, sguwh, sguwl, n4);
        split_kernel<<<(n4 + 255)/256, 256>>>(suw, sguwh + (size_t)ISH*H_DIM,
                                              sguwl + (size_t)ISH*H_DIM, n4);
        n4 = H_DIM*ISH/4;
        split_kernel<<<(n4 + 255)/256, 256>>>(sdw, sdwh, sdwl, n4);
        n4 = NE*2*IDIM*H_DIM/4;
        split_kernel<<<(n4 + 255)/256, 256>>>(gup, guph, gupl, n4);
        n4 = NE*H_DIM*IDIM/4;
        split_kernel<<<(n4 + 255)/256, 256>>>(dwn, dwnh, dwnl, n4);
    }

    // shared expert: sgu = x @ [Wg;Wu]^T (N=2048), silu*up -> smid, out = smid@Wd^T
    gemm_bf<0><<<dim3(2*ISH/128, T_TOK/128, 1), 256, GEMM_SMEM>>>(
        xh, xl, sguwh, sguwl, sgu, T_TOK, 2*ISH, H_DIM);
    silu_mul_shared_kernel<<<(T_TOK*ISH/2 + 255)/256, 256>>>();
    gemm_bf<0><<<dim3(H_DIM/128, T_TOK/128, 1), 256, GEMM_SMEM>>>(
        smh, sml, sdwh, sdwl, out, T_TOK, H_DIM, ISH);

    // grouped experts
    gemm_bf<1><<<dim3(2*IDIM/128, CAP/128, NE), 256, GEMM_SMEM>>>(
        xh, xl, guph, gupl, gu, CAP, 2*IDIM, H_DIM);
    silu_mul_grouped_kernel<<<(NPAIR*IDIM/2 + 255)/256, 256>>>();
    gemm_bf<2><<<dim3(H_DIM/128, CAP/128, NE), 256, GEMM_SMEM>>>(
        hmh, hml, dwnh, dwnl, y, CAP, H_DIM, IDIM);

    // deterministic combine
    combine_kernel<<<dim3(T_TOK, H_DIM/256), 256>>>(out);

    (void)in_sizes; (void)n_in; (void)out_size;
}

// round 9
// speedup vs baseline: 1.0436x; 1.0436x over previous
#include <cuda_runtime.h>
#include <cuda_bf16.h>
#include <cstdint>
#include <math.h>

#define T_TOK 2048
#define H_DIM 1024
#define NE    32
#define IDIM  512
#define K_TOP 6
#define ISH   1024
#define CAP   2048
#define NPAIR (T_TOK*K_TOP)   // 12288

typedef __nv_bfloat16 bf16;

// ---------------- scratch (static device globals; no runtime alloc) ----------
__device__ int   g_counts[NE];
__device__ int   g_offsets[NE];
__device__ int   g_bucket[NE*CAP];
__device__ int   g_topidx[NPAIR];
__device__ float g_topw[NPAIR];
__device__ int   g_slot[NPAIR];

// bf16 hi/lo planes for ACTIVATIONS only (weights stay fp32, split in-GEMM)
__device__ bf16  g_x_hi   [(size_t)T_TOK*H_DIM],   g_x_lo   [(size_t)T_TOK*H_DIM];
__device__ bf16  g_smid_hi[(size_t)T_TOK*ISH],     g_smid_lo[(size_t)T_TOK*ISH];
__device__ bf16  g_hmid_hi[(size_t)NPAIR*IDIM],    g_hmid_lo[(size_t)NPAIR*IDIM];
// fp32 GEMM outputs
__device__ float g_sg [(size_t)T_TOK*ISH];
__device__ float g_su [(size_t)T_TOK*ISH];
__device__ float g_gu [(size_t)NPAIR*2*IDIM];
__device__ float g_y  [(size_t)NPAIR*H_DIM];

__device__ __forceinline__ float silu_f(float v){ return v / (1.f + __expf(-v)); }

__device__ __forceinline__ uint32_t smem_u32(const void* p){
    uint32_t a;
    asm("{ .reg .u64 t; cvta.to.shared.u64 t, %1; cvt.u32.u64 %0, t; }"
        : "=r"(a) : "l"(p));
    return a;
}

__device__ __forceinline__ void cpa16(uint32_t dst, const void* src, bool valid){
    asm volatile("cp.async.cg.shared.global [%0], [%1], 16, %2;"
                 :: "r"(dst), "l"(src), "r"(valid ? 16u : 0u) : "memory");
}
#define CPA_COMMIT() asm volatile("cp.async.commit_group;" ::: "memory")
#define CPA_WAIT1()  asm volatile("cp.async.wait_group 1;" ::: "memory")
#define CPA_WAIT0()  asm volatile("cp.async.wait_group 0;" ::: "memory")

__device__ __forceinline__ void mma16(float* c, const uint32_t* a, const uint32_t* b){
    asm volatile("mma.sync.aligned.m16n8k16.row.col.f32.bf16.bf16.f32 "
                 "{%0,%1,%2,%3}, {%4,%5,%6,%7}, {%8,%9}, {%0,%1,%2,%3};"
                 : "+f"(c[0]), "+f"(c[1]), "+f"(c[2]), "+f"(c[3])
                 : "r"(a[0]), "r"(a[1]), "r"(a[2]), "r"(a[3]),
                   "r"(b[0]), "r"(b[1]));
}

// split float2 -> bf16x2 hi (low half = first elem) + bf16x2 lo
__device__ __forceinline__ void split2(float2 f, uint32_t& hi, uint32_t& lo){
    asm("cvt.rn.bf16x2.f32 %0, %1, %2;" : "=r"(hi) : "f"(f.y), "f"(f.x));
    float h0 = __uint_as_float(hi << 16);
    float h1 = __uint_as_float(hi & 0xFFFF0000u);
    float l0 = f.x - h0, l1 = f.y - h1;
    asm("cvt.rn.bf16x2.f32 %0, %1, %2;" : "=r"(lo) : "f"(l1), "f"(l0));
}

#define STS128(addr, r0, r1, r2, r3) \
    asm volatile("st.shared.v4.b32 [%0], {%1,%2,%3,%4};" \
                 :: "r"(addr), "r"(r0), "r"(r1), "r"(r2), "r"(r3) : "memory")

// swizzled bf16x2 (pair) load from plane: row stride 64B, unit swizzle ^(row>>1)&3
__device__ __forceinline__ uint32_t ldp(const char* plane, int row, int pair){
    return *(const uint32_t*)(plane + row*64 + 4*(pair ^ (((row >> 1) & 3) << 2)));
}

// ======================= hybrid hi/lo bf16 GEMM ==============================
// C[m,n] = sum_k A[m,k]*B[n,k]
// A: pre-split bf16 hi/lo planes (activations), cp.async'd.
// B: fp32 weights, LDG-prefetched, split in registers, STS.128'd to planes.
// CTA 128x128, BK=32, 256 thr = 8 warps (2m x 4n), warp tile 64x32.
// smem/buffer: Ah 8K | Al 8K | Bh 8K | Bl 8K = 32KB, double buffered = 64KB.
// MODE 0: dense; MODE 1: grouped gather via g_bucket; MODE 2: grouped compact.

#define GEMM_SMEM 65536

template<int MODE>
__global__ __launch_bounds__(256, 2)
void gemm_hl(const bf16* __restrict__ Ahi, const bf16* __restrict__ Alo,
             const float* __restrict__ W, float* __restrict__ C,
             int M, int N, int K)
{
    int e = 0, cnt = M, off = 0;
    size_t woff = 0;
    if (MODE){
        e = blockIdx.z;
        cnt = g_counts[e];
        if ((int)blockIdx.y * 128 >= cnt) return;
        off = g_offsets[e];
        woff = (size_t)e * N * K;
    }
    const int m0 = blockIdx.y * 128, n0 = blockIdx.x * 128;

    extern __shared__ char sm[];
    const uint32_t sb = smem_u32(sm);

    const int tid = threadIdx.x, warp = tid >> 5, lane = tid & 31;
    const int wm = (warp >> 2) * 64, wn = (warp & 3) * 32;
    const int r4 = lane >> 2, c2 = lane & 3;

    // ---- load setup: thread owns row lr, half hh (k[16hh..16hh+16)) ----
    const int lr = tid >> 1, hh = tid & 1;
    const int m = m0 + lr;
    bool avalid; size_t garow;
    if (MODE == 0){ avalid = true; garow = (size_t)m; }
    else if (MODE == 1){ avalid = m < cnt; garow = avalid ? (size_t)g_bucket[e*CAP + m] : 0; }
    else { avalid = m < cnt; garow = (size_t)(off + (avalid ? m : 0)); }

    const bf16*  a_hi = Ahi + garow * (size_t)K + hh*16;
    const bf16*  a_lo = Alo + garow * (size_t)K + hh*16;
    const float* bw   = W + woff + (size_t)(n0 + lr) * K + hh*16;

    const uint32_t swz = (uint32_t)((lr >> 1) & 3);
    const uint32_t u0 = (uint32_t)((2*hh)     ^ swz);
    const uint32_t u1 = (uint32_t)((2*hh + 1) ^ swz);
    const uint32_t dA0 = (uint32_t)(lr*64 + 16*u0), dA1 = (uint32_t)(lr*64 + 16*u1);

    float acc[4][4][4];
    #pragma unroll
    for (int a = 0; a < 4; a++)
    #pragma unroll
    for (int b = 0; b < 4; b++)
    #pragma unroll
    for (int q = 0; q < 4; q++) acc[a][b][q] = 0.f;

    const int nk = K >> 5;

    // prologue: LDG B(0); cp.async A(0) -> buffer 0
    float4 rb0 = *(const float4*)bw;
    float4 rb1 = *(const float4*)(bw + 4);
    float4 rb2 = *(const float4*)(bw + 8);
    float4 rb3 = *(const float4*)(bw + 12);
    cpa16(sb + dA0,        a_hi,     avalid);
    cpa16(sb + dA1,        a_hi + 8, avalid);
    cpa16(sb + 8192 + dA0, a_lo,     avalid);
    cpa16(sb + 8192 + dA1, a_lo + 8, avalid);
    CPA_COMMIT();

    for (int ch = 0; ch < nk; ch++){
        const int b = ch & 1;
        const uint32_t base = sb + (uint32_t)(b * 32768);

        // store B(ch): split 16 fp32 -> hi/lo planes, 2x STS.128 each
        {
            uint32_t h0,h1,h2,h3,h4,h5,h6,h7, l0,l1,l2,l3,l4,l5,l6,l7;
            split2(make_float2(rb0.x, rb0.y), h0, l0);
            split2(make_float2(rb0.z, rb0.w), h1, l1);
            split2(make_float2(rb1.x, rb1.y), h2, l2);
            split2(make_float2(rb1.z, rb1.w), h3, l3);
            split2(make_float2(rb2.x, rb2.y), h4, l4);
            split2(make_float2(rb2.z, rb2.w), h5, l5);
            split2(make_float2(rb3.x, rb3.y), h6, l6);
            split2(make_float2(rb3.z, rb3.w), h7, l7);
            STS128(base + 16384 + lr*64 + 16*u0, h0, h1, h2, h3);
            STS128(base + 16384 + lr*64 + 16*u1, h4, h5, h6, h7);
            STS128(base + 24576 + lr*64 + 16*u0, l0, l1, l2, l3);
            STS128(base + 24576 + lr*64 + 16*u1, l4, l5, l6, l7);
        }

        if (ch + 1 < nk){
            const int ko = (ch + 1) << 5;
            rb0 = *(const float4*)(bw + ko);
            rb1 = *(const float4*)(bw + ko + 4);
            rb2 = *(const float4*)(bw + ko + 8);
            rb3 = *(const float4*)(bw + ko + 12);
            const uint32_t nb = sb + (uint32_t)(((ch + 1) & 1) * 32768);
            cpa16(nb + dA0,        a_hi + ko,     avalid);
            cpa16(nb + dA1,        a_hi + ko + 8, avalid);
            cpa16(nb + 8192 + dA0, a_lo + ko,     avalid);
            cpa16(nb + 8192 + dA1, a_lo + ko + 8, avalid);
            CPA_COMMIT();
            CPA_WAIT1();
        } else {
            CPA_WAIT0();
        }
        __syncthreads();

        const char* pAh = sm + b*32768;
        const char* pAl = pAh + 8192;
        const char* pBh = pAh + 16384;
        const char* pBl = pAh + 24576;

        #pragma unroll
        for (int ks = 0; ks < 2; ks++){
            const int pb = ks*8 + c2;
            uint32_t bh[4][2], bl[4][2];
            #pragma unroll
            for (int nf = 0; nf < 4; nf++){
                const int nr = wn + nf*8 + r4;
                bh[nf][0] = ldp(pBh, nr, pb); bh[nf][1] = ldp(pBh, nr, pb + 4);
                bl[nf][0] = ldp(pBl, nr, pb); bl[nf][1] = ldp(pBl, nr, pb + 4);
            }
            #pragma unroll
            for (int mf = 0; mf < 4; mf++){
                const int mr = wm + mf*16 + r4;
                uint32_t ah[4], al[4];
                ah[0] = ldp(pAh, mr,     pb);     ah[1] = ldp(pAh, mr + 8, pb);
                ah[2] = ldp(pAh, mr,     pb + 4); ah[3] = ldp(pAh, mr + 8, pb + 4);
                al[0] = ldp(pAl, mr,     pb);     al[1] = ldp(pAl, mr + 8, pb);
                al[2] = ldp(pAl, mr,     pb + 4); al[3] = ldp(pAl, mr + 8, pb + 4);
                #pragma unroll
                for (int nf = 0; nf < 4; nf++){
                    mma16(acc[mf][nf], ah, bh[nf]);
                    mma16(acc[mf][nf], ah, bl[nf]);
                    mma16(acc[mf][nf], al, bh[nf]);
                }
            }
        }
        __syncthreads();
    }

    // epilogue
    #pragma unroll
    for (int mf = 0; mf < 4; mf++){
        const int rl = wm + mf*16 + r4;
        #pragma unroll
        for (int half = 0; half < 2; half++){
            const int rloc = rl + half*8;
            bool valid; size_t crow;
            if (MODE == 0){ valid = true; crow = (size_t)(m0 + rloc); }
            else { valid = (m0 + rloc) < cnt; crow = (size_t)(off + m0 + rloc); }
            if (valid){
                float* cp = C + crow * N + n0 + wn + c2*2;
                #pragma unroll
                for (int nf = 0; nf < 4; nf++){
                    float2 v;
                    v.x = acc[mf][nf][half*2 + 0];
                    v.y = acc[mf][nf][half*2 + 1];
                    *(float2*)(cp + nf*8) = v;
                }
            }
        }
    }
}

// ---------------- split pass: fp32 -> bf16 hi/lo planes (activations) --------
__global__ void split_kernel(const float* __restrict__ src,
                             bf16* __restrict__ hi, bf16* __restrict__ lo, int n4)
{
    int i = blockIdx.x * blockDim.x + threadIdx.x;
    if (i < n4){
        float4 v = ((const float4*)src)[i];
        uint32_t h01, l01, h23, l23;
        split2(make_float2(v.x, v.y), h01, l01);
        split2(make_float2(v.z, v.w), h23, l23);
        ((uint2*)hi)[i] = make_uint2(h01, h23);
        ((uint2*)lo)[i] = make_uint2(l01, l23);
    }
}

// ---------------- router: softmax + bias + top-6 + bucketing ----------------
__global__ void zero_counts_kernel(){
    if (threadIdx.x < NE) g_counts[threadIdx.x] = 0;
}

__global__ void router_kernel(const float* __restrict__ x,
                              const float* __restrict__ rw,
                              const float* __restrict__ bias)
{
    __shared__ float sx[H_DIM];
    __shared__ float slog[NE];
    const int t = blockIdx.x;
    const float* xr = x + (size_t)t * H_DIM;
    for (int i = threadIdx.x; i < H_DIM; i += blockDim.x) sx[i] = xr[i];
    __syncthreads();

    const int warp = threadIdx.x >> 5, lane = threadIdx.x & 31;
    for (int e = warp*8; e < warp*8 + 8; e++){
        const float* w = rw + (size_t)e * H_DIM;
        float s = 0.f;
        for (int h = lane; h < H_DIM; h += 32) s += sx[h] * w[h];
        #pragma unroll
        for (int o = 16; o; o >>= 1) s += __shfl_xor_sync(0xffffffffu, s, o);
        if (lane == 0) slog[e] = s;
    }
    __syncthreads();

    if (threadIdx.x == 0){
        float mx = -1e30f;
        for (int e = 0; e < NE; e++) mx = fmaxf(mx, slog[e]);
        float p[NE]; float sum = 0.f;
        for (int e = 0; e < NE; e++){ p[e] = expf(slog[e] - mx); sum += p[e]; }
        float inv = 1.f / sum;
        float corr[NE];
        for (int e = 0; e < NE; e++){ p[e] *= inv; corr[e] = p[e] + bias[e]; }

        int idx[K_TOP]; bool used[NE];
        for (int e = 0; e < NE; e++) used[e] = false;
        for (int k = 0; k < K_TOP; k++){
            int best = -1; float bv = -1e30f;
            for (int e = 0; e < NE; e++)
                if (!used[e] && corr[e] > bv){ bv = corr[e]; best = e; }
            used[best] = true; idx[k] = best;
        }
        float wsum = 0.f;
        for (int k = 0; k < K_TOP; k++) wsum += p[idx[k]];
        wsum = fmaxf(wsum, 1e-12f);
        for (int k = 0; k < K_TOP; k++){
            int e = idx[k];
            float wn = p[e] / wsum;
            int slot = atomicAdd(&g_counts[e], 1);
            g_bucket[e*CAP + slot] = t;
            g_topidx[t*K_TOP + k] = e;
            g_topw [t*K_TOP + k] = wn;
            g_slot [t*K_TOP + k] = slot;
        }
    }
}

__global__ void scan_kernel(){
    if (threadIdx.x == 0){
        int s = 0;
        for (int e = 0; e < NE; e++){ g_offsets[e] = s; s += g_counts[e]; }
    }
}

// ---------------- elementwise (fused split outputs) --------------------------
__global__ void silu_mul_shared_kernel(){
    int i = blockIdx.x * blockDim.x + threadIdx.x;   // over T*ISH/2
    if (i < T_TOK*ISH/2){
        float2 g = ((const float2*)g_sg)[i];
        float2 u = ((const float2*)g_su)[i];
        float2 r;
        r.x = silu_f(g.x) * u.x;
        r.y = silu_f(g.y) * u.y;
        uint32_t h, l;
        split2(r, h, l);
        ((uint32_t*)g_smid_hi)[i] = h;
        ((uint32_t*)g_smid_lo)[i] = l;
    }
}

__global__ void silu_mul_grouped_kernel(){
    int i = blockIdx.x * blockDim.x + threadIdx.x;   // over NPAIR*IDIM/2
    if (i < NPAIR*IDIM/2){
        int p = i / (IDIM/2), c = (i % (IDIM/2)) * 2;
        const float* row = g_gu + (size_t)p * 2 * IDIM;
        float2 r;
        r.x = silu_f(row[c])     * row[IDIM + c];
        r.y = silu_f(row[c + 1]) * row[IDIM + c + 1];
        uint32_t h, l;
        split2(r, h, l);
        ((uint32_t*)g_hmid_hi)[(size_t)p*(IDIM/2) + (c>>1)] = h;
        ((uint32_t*)g_hmid_lo)[(size_t)p*(IDIM/2) + (c>>1)] = l;
    }
}

// ---------------- combine: deterministic per-token sum of 6 expert rows ------
__global__ void combine_kernel(float* __restrict__ out){
    const int t = blockIdx.x;
    const int h = blockIdx.y * 256 + threadIdx.x;
    float acc = 0.f;
    #pragma unroll
    for (int k = 0; k < K_TOP; k++){
        int e    = g_topidx[t*K_TOP + k];
        float w  = g_topw [t*K_TOP + k];
        int row  = g_offsets[e] + g_slot[t*K_TOP + k];
        acc += w * g_y[(size_t)row * H_DIM + h];
    }
    out[(size_t)t * H_DIM + h] += acc;   // out already holds shared_out
}

// ---------------- launch ------------------------------------------------------
static void* sym(const void* s){ void* p; cudaGetSymbolAddress(&p, s); return p; }

extern "C" void kernel_launch(void* const* d_in, const int* in_sizes, int n_in,
                              void* d_out, int out_size)
{
    const float* x    = (const float*)d_in[0];
    const float* rw   = (const float*)d_in[1];
    const float* bias = (const float*)d_in[2];
    const float* gup  = (const float*)d_in[3];
    const float* dwn  = (const float*)d_in[4];
    const float* sgw  = (const float*)d_in[5];
    const float* suw  = (const float*)d_in[6];
    const float* sdw  = (const float*)d_in[7];
    float* out = (float*)d_out;

    bf16 *xh = (bf16*)sym(g_x_hi), *xl = (bf16*)sym(g_x_lo);
    bf16 *smh = (bf16*)sym(g_smid_hi), *sml = (bf16*)sym(g_smid_lo);
    bf16 *hmh = (bf16*)sym(g_hmid_hi), *hml = (bf16*)sym(g_hmid_lo);
    float *sg = (float*)sym(g_sg), *su = (float*)sym(g_su);
    float *gu = (float*)sym(g_gu), *y = (float*)sym(g_y);

    cudaFuncSetAttribute(gemm_hl<0>, cudaFuncAttributeMaxDynamicSharedMemorySize, GEMM_SMEM);
    cudaFuncSetAttribute(gemm_hl<1>, cudaFuncAttributeMaxDynamicSharedMemorySize, GEMM_SMEM);
    cudaFuncSetAttribute(gemm_hl<2>, cudaFuncAttributeMaxDynamicSharedMemorySize, GEMM_SMEM);

    // routing
    zero_counts_kernel<<<1, 32>>>();
    router_kernel<<<T_TOK, 128>>>(x, rw, bias);
    scan_kernel<<<1, 32>>>();

    // split x (activations only; weights are split in-GEMM)
    {
        int n4 = T_TOK*H_DIM/4;
        split_kernel<<<(n4 + 255)/256, 256>>>(x, xh, xl, n4);
    }

    // shared expert
    gemm_hl<0><<<dim3(ISH/128, T_TOK/128, 1), 256, GEMM_SMEM>>>(
        xh, xl, sgw, sg, T_TOK, ISH, H_DIM);
    gemm_hl<0><<<dim3(ISH/128, T_TOK/128, 1), 256, GEMM_SMEM>>>(
        xh, xl, suw, su, T_TOK, ISH, H_DIM);
    silu_mul_shared_kernel<<<(T_TOK*ISH/2 + 255)/256, 256>>>();
    gemm_hl<0><<<dim3(H_DIM/128, T_TOK/128, 1), 256, GEMM_SMEM>>>(
        smh, sml, sdw, out, T_TOK, H_DIM, ISH);

    // grouped experts
    gemm_hl<1><<<dim3(2*IDIM/128, CAP/128, NE), 256, GEMM_SMEM>>>(
        xh, xl, gup, gu, CAP, 2*IDIM, H_DIM);
    silu_mul_grouped_kernel<<<(NPAIR*IDIM/2 + 255)/256, 256>>>();
    gemm_hl<2><<<dim3(H_DIM/128, CAP/128, NE), 256, GEMM_SMEM>>>(
        hmh, hml, dwn, y, CAP, H_DIM, IDIM);

    // deterministic combine
    combine_kernel<<<dim3(T_TOK, H_DIM/256), 256>>>(out);

    (void)in_sizes; (void)n_in; (void)out_size;
}

// round 11
// speedup vs baseline: 1.1152x; 1.0686x over previous
#include <cuda_runtime.h>
#include <cstdint>
#include <math.h>

#define T_TOK 2048
#define H_DIM 1024
#define NE    32
#define IDIM  512
#define K_TOP 6
#define ISH   1024
#define CAP   2048
#define NPAIR (T_TOK*K_TOP)   // 12288

// ---------------- scratch (static device globals; no runtime alloc) ----------
__device__ int   g_counts[NE];
__device__ int   g_offsets[NE];
__device__ int   g_bucket[NE*CAP];
__device__ int   g_topidx[NPAIR];
__device__ float g_topw[NPAIR];
__device__ int   g_slot[NPAIR];
__device__ float g_sg  [(size_t)T_TOK*ISH];
__device__ float g_su  [(size_t)T_TOK*ISH];
__device__ float g_smid[(size_t)T_TOK*ISH];
__device__ float g_gu  [(size_t)NPAIR*2*IDIM];
__device__ float g_hmid[(size_t)NPAIR*IDIM];
__device__ float g_y   [(size_t)NPAIR*H_DIM];

__device__ __forceinline__ float silu_f(float v){ return v / (1.f + __expf(-v)); }

__device__ __forceinline__ uint32_t smem_u32(const void* p){
    uint32_t a;
    asm("{ .reg .u64 t; cvta.to.shared.u64 t, %1; cvt.u32.u64 %0, t; }"
        : "=r"(a) : "l"(p));
    return a;
}

__device__ __forceinline__ void cpa16(uint32_t dst, const void* src, bool valid){
    asm volatile("cp.async.cg.shared.global [%0], [%1], 16, %2;"
                 :: "r"(dst), "l"(src), "r"(valid ? 16u : 0u) : "memory");
}
#define CPA_COMMIT() asm volatile("cp.async.commit_group;" ::: "memory")
#define CPA_WAIT1()  asm volatile("cp.async.wait_group 1;" ::: "memory")
#define CPA_WAIT0()  asm volatile("cp.async.wait_group 0;" ::: "memory")

// bf16 m16n8k16 mma, fp32 accumulate
__device__ __forceinline__ void mma16(float* c, const uint32_t* a, const uint32_t* b){
    asm volatile("mma.sync.aligned.m16n8k16.row.col.f32.bf16.bf16.f32 "
                 "{%0,%1,%2,%3}, {%4,%5,%6,%7}, {%8,%9}, {%0,%1,%2,%3};"
                 : "+f"(c[0]), "+f"(c[1]), "+f"(c[2]), "+f"(c[3])
                 : "r"(a[0]), "r"(a[1]), "r"(a[2]), "r"(a[3]),
                   "r"(b[0]), "r"(b[1]));
}

// split a float2 (consecutive k) into bf16x2 hi + bf16x2 lo (low half = first k)
__device__ __forceinline__ void split2(float2 f, uint32_t& hi, uint32_t& lo){
    asm("cvt.rn.bf16x2.f32 %0, %1, %2;" : "=r"(hi) : "f"(f.y), "f"(f.x));
    float h0 = __uint_as_float(hi << 16);
    float h1 = __uint_as_float(hi & 0xFFFF0000u);
    float l0 = f.x - h0, l1 = f.y - h1;
    asm("cvt.rn.bf16x2.f32 %0, %1, %2;" : "=r"(lo) : "f"(l1), "f"(l0));
}

// swizzled float2 load from a 32-float-wide smem tile
// store-side swizzle: col4 ^= (row&3)<<1 (16B units) => float col ^= (row&3)<<3
__device__ __forceinline__ float2 lds2(const float* base, int row, int col){
    int idx = row*32 + (col ^ ((row & 3) << 3));
    return *(const float2*)(base + idx);
}

// ======================= 3xBF16 mma.sync GEMM (128x64 tile) ==================
// C[m,n] = sum_k A[m,k] * B[n,k]   (A, B both K-contiguous, fp32)
// CTA tile 128x64, BK=32, 256 threads = 8 warps (4m x 2n), warp tile 32x32.
// acc = 32 regs/thread -> __launch_bounds__(256,2) = 2 CTAs/SM.
// fp32 tiles in smem via cp.async (double-buffered); fragments split into
// bf16 hi/lo in registers; D = Ahi*Bhi + Ahi*Blo + Alo*Bhi (fp32 accum).
// smem: A0 16K | A1 16K | B0 8K | B1 8K = 48KB.
// MODE 0: dense; MODE 1: grouped gather via g_bucket; MODE 2: grouped compact.

#define GEMM_SMEM 49152

template<int MODE>
__global__ __launch_bounds__(256, 2)
void gemm_mma(const float* __restrict__ A, const float* __restrict__ W,
              float* __restrict__ C, int M, int N, int K)
{
    int e = 0, cnt = M, off = 0;
    const float* Wp = W;
    if (MODE){
        e = blockIdx.z;
        cnt = g_counts[e];
        if ((int)blockIdx.y * 128 >= cnt) return;
        off = g_offsets[e];
        Wp += (size_t)e * N * K;
    }
    const int m0 = blockIdx.y * 128, n0 = blockIdx.x * 64;

    extern __shared__ float smf[];   // A0[4096] A1[4096] B0[2048] B1[2048]
    const uint32_t sb = smem_u32(smf);

    const int tid = threadIdx.x, warp = tid >> 5, lane = tid & 31;
    const int wm = (warp & 3) * 32, wn = (warp >> 2) * 32;
    const int r4 = lane >> 2, c2 = lane & 3;

    // global load setup: A 4 rows/thread, B 2 rows/thread
    const int lr0 = tid >> 3, c4 = tid & 7;
    const float* ap[4]; bool av[4]; uint32_t soA[4];
    #pragma unroll
    for (int j = 0; j < 4; j++){
        int r = lr0 + j*32;
        soA[j] = (uint32_t)(r*128 + ((c4 ^ ((r & 3) << 1)) << 4));
        int m = m0 + r;
        size_t garow;
        if (MODE == 0){ av[j] = true; garow = (size_t)m; }
        else if (MODE == 1){ av[j] = m < cnt; garow = av[j] ? (size_t)g_bucket[e*CAP + m] : 0; }
        else { av[j] = m < cnt; garow = (size_t)(off + (av[j] ? m : 0)); }
        ap[j] = A + garow * (size_t)K + c4*4;
    }
    const float* bp[2]; uint32_t soB[2];
    #pragma unroll
    for (int j = 0; j < 2; j++){
        int r = lr0 + j*32;                      // 0..63
        soB[j] = (uint32_t)(r*128 + ((c4 ^ ((r & 3) << 1)) << 4));
        bp[j] = Wp + (size_t)(n0 + r) * K + c4*4;
    }

    float acc[2][4][4];
    #pragma unroll
    for (int a = 0; a < 2; a++)
    #pragma unroll
    for (int b = 0; b < 4; b++)
    #pragma unroll
    for (int q = 0; q < 4; q++) acc[a][b][q] = 0.f;

    const int nk = K >> 5;

    // prologue: chunk 0 -> buf 0   (A at 0, B at float offset 8192)
    #pragma unroll
    for (int j = 0; j < 4; j++) cpa16(sb + soA[j], ap[j], av[j]);
    #pragma unroll
    for (int j = 0; j < 2; j++) cpa16(sb + 32768 + soB[j], bp[j], true);
    CPA_COMMIT();

    for (int ch = 0; ch < nk; ch++){
        const int b = ch & 1;
        if (ch + 1 < nk){
            const int nb = (ch + 1) & 1;
            const int ko = (ch + 1) << 5;
            #pragma unroll
            for (int j = 0; j < 4; j++)
                cpa16(sb + (uint32_t)(nb*16384) + soA[j], ap[j] + ko, av[j]);
            #pragma unroll
            for (int j = 0; j < 2; j++)
                cpa16(sb + 32768 + (uint32_t)(nb*8192) + soB[j], bp[j] + ko, true);
            CPA_COMMIT();
            CPA_WAIT1();
        } else {
            CPA_WAIT0();
        }
        __syncthreads();

        const float* Ab = smf + b * 4096;
        const float* Bb = smf + 8192 + b * 2048;

        #pragma unroll
        for (int ks = 0; ks < 2; ks++){
            const int kb = ks * 16 + 2*c2;
            // B fragments for 4 n-tiles (warp covers 32 n), split hi/lo
            uint32_t bhi[4][2], blo[4][2];
            #pragma unroll
            for (int nf = 0; nf < 4; nf++){
                const int nr = wn + nf*8 + r4;
                split2(lds2(Bb, nr, kb),     bhi[nf][0], blo[nf][0]);
                split2(lds2(Bb, nr, kb + 8), bhi[nf][1], blo[nf][1]);
            }
            #pragma unroll
            for (int mf = 0; mf < 2; mf++){
                const int mr = wm + mf*16 + r4;
                uint32_t ahi[4], alo[4];
                split2(lds2(Ab, mr,     kb),     ahi[0], alo[0]);
                split2(lds2(Ab, mr + 8, kb),     ahi[1], alo[1]);
                split2(lds2(Ab, mr,     kb + 8), ahi[2], alo[2]);
                split2(lds2(Ab, mr + 8, kb + 8), ahi[3], alo[3]);
                #pragma unroll
                for (int nf = 0; nf < 4; nf++){
                    mma16(acc[mf][nf], ahi, bhi[nf]);
                    mma16(acc[mf][nf], ahi, blo[nf]);
                    mma16(acc[mf][nf], alo, bhi[nf]);
                }
            }
        }
        __syncthreads();
    }

    // epilogue: c0,c1 at (row, col..col+1); c2,c3 at (row+8, col..col+1)
    #pragma unroll
    for (int mf = 0; mf < 2; mf++){
        const int rl = wm + mf*16 + r4;
        #pragma unroll
        for (int half = 0; half < 2; half++){
            const int rloc = rl + half*8;
            bool valid; size_t crow;
            if (MODE == 0){ valid = (m0 + rloc) < M; crow = (size_t)(m0 + rloc); }
            else { valid = rloc < (cnt - m0); crow = (size_t)(off + m0 + rloc); }
            if (valid){
                float* cp = C + crow * N + n0 + wn + c2*2;
                #pragma unroll
                for (int nf = 0; nf < 4; nf++){
                    float2 v;
                    v.x = acc[mf][nf][half*2 + 0];
                    v.y = acc[mf][nf][half*2 + 1];
                    *(float2*)(cp + nf*8) = v;
                }
            }
        }
    }
}

// ---------------- router: softmax + bias + top-6 + bucketing ----------------
__global__ void zero_counts_kernel(){
    if (threadIdx.x < NE) g_counts[threadIdx.x] = 0;
}

__global__ void router_kernel(const float* __restrict__ x,
                              const float* __restrict__ rw,
                              const float* __restrict__ bias)
{
    __shared__ float sx[H_DIM];
    __shared__ float slog[NE];
    const int t = blockIdx.x;
    const float* xr = x + (size_t)t * H_DIM;
    for (int i = threadIdx.x; i < H_DIM; i += blockDim.x) sx[i] = xr[i];
    __syncthreads();

    const int warp = threadIdx.x >> 5, lane = threadIdx.x & 31;
    for (int e = warp*8; e < warp*8 + 8; e++){
        const float* w = rw + (size_t)e * H_DIM;
        float s = 0.f;
        for (int h = lane; h < H_DIM; h += 32) s += sx[h] * w[h];
        #pragma unroll
        for (int o = 16; o; o >>= 1) s += __shfl_xor_sync(0xffffffffu, s, o);
        if (lane == 0) slog[e] = s;
    }
    __syncthreads();

    if (threadIdx.x == 0){
        float mx = -1e30f;
        for (int e = 0; e < NE; e++) mx = fmaxf(mx, slog[e]);
        float p[NE]; float sum = 0.f;
        for (int e = 0; e < NE; e++){ p[e] = expf(slog[e] - mx); sum += p[e]; }
        float inv = 1.f / sum;
        float corr[NE];
        for (int e = 0; e < NE; e++){ p[e] *= inv; corr[e] = p[e] + bias[e]; }

        int idx[K_TOP]; bool used[NE];
        for (int e = 0; e < NE; e++) used[e] = false;
        for (int k = 0; k < K_TOP; k++){
            int best = -1; float bv = -1e30f;
            for (int e = 0; e < NE; e++)
                if (!used[e] && corr[e] > bv){ bv = corr[e]; best = e; }
            used[best] = true; idx[k] = best;
        }
        float wsum = 0.f;
        for (int k = 0; k < K_TOP; k++) wsum += p[idx[k]];
        wsum = fmaxf(wsum, 1e-12f);
        for (int k = 0; k < K_TOP; k++){
            int e = idx[k];
            float wn = p[e] / wsum;
            int slot = atomicAdd(&g_counts[e], 1);
            g_bucket[e*CAP + slot] = t;
            g_topidx[t*K_TOP + k] = e;
            g_topw [t*K_TOP + k] = wn;
            g_slot [t*K_TOP + k] = slot;
        }
    }
}

__global__ void scan_kernel(){
    if (threadIdx.x == 0){
        int s = 0;
        for (int e = 0; e < NE; e++){ g_offsets[e] = s; s += g_counts[e]; }
    }
}

// ---------------- elementwise -------------------------------------------------
__global__ void silu_mul_shared_kernel(){
    size_t i = (size_t)blockIdx.x * blockDim.x + threadIdx.x;
    if (i < (size_t)T_TOK * ISH)
        g_smid[i] = silu_f(g_sg[i]) * g_su[i];
}

__global__ void silu_mul_grouped_kernel(){
    size_t i = (size_t)blockIdx.x * blockDim.x + threadIdx.x;
    if (i < (size_t)NPAIR * IDIM){
        size_t p = i / IDIM, c = i % IDIM;
        g_hmid[i] = silu_f(g_gu[p*2*IDIM + c]) * g_gu[p*2*IDIM + IDIM + c];
    }
}

// ---------------- combine: deterministic per-token sum of 6 expert rows ------
__global__ void combine_kernel(float* __restrict__ out){
    const int t = blockIdx.x;
    const int h = blockIdx.y * 256 + threadIdx.x;
    float acc = 0.f;
    #pragma unroll
    for (int k = 0; k < K_TOP; k++){
        int e    = g_topidx[t*K_TOP + k];
        float w  = g_topw [t*K_TOP + k];
        int row  = g_offsets[e] + g_slot[t*K_TOP + k];
        acc += w * g_y[(size_t)row * H_DIM + h];
    }
    out[(size_t)t * H_DIM + h] += acc;   // out already holds shared_out
}

// ---------------- launch ------------------------------------------------------
static void* sym(const void* s){ void* p; cudaGetSymbolAddress(&p, s); return p; }

extern "C" void kernel_launch(void* const* d_in, const int* in_sizes, int n_in,
                              void* d_out, int out_size)
{
    const float* x    = (const float*)d_in[0];
    const float* rw   = (const float*)d_in[1];
    const float* bias = (const float*)d_in[2];
    const float* gup  = (const float*)d_in[3];
    const float* dwn  = (const float*)d_in[4];
    const float* sgw  = (const float*)d_in[5];
    const float* suw  = (const float*)d_in[6];
    const float* sdw  = (const float*)d_in[7];
    float* out = (float*)d_out;

    float *sg = (float*)sym(g_sg), *su = (float*)sym(g_su);
    float *smid = (float*)sym(g_smid);
    float *gu = (float*)sym(g_gu), *hmid = (float*)sym(g_hmid);
    float *y = (float*)sym(g_y);

    cudaFuncSetAttribute(gemm_mma<0>, cudaFuncAttributeMaxDynamicSharedMemorySize, GEMM_SMEM);
    cudaFuncSetAttribute(gemm_mma<1>, cudaFuncAttributeMaxDynamicSharedMemorySize, GEMM_SMEM);
    cudaFuncSetAttribute(gemm_mma<2>, cudaFuncAttributeMaxDynamicSharedMemorySize, GEMM_SMEM);

    // routing
    zero_counts_kernel<<<1, 32>>>();
    router_kernel<<<T_TOK, 128>>>(x, rw, bias);
    scan_kernel<<<1, 32>>>();

    // shared expert: sg = x@Wg^T, su = x@Wu^T, smid = silu(sg)*su, out = smid@Wd^T
    gemm_mma<0><<<dim3(ISH/64, T_TOK/128, 1), 256, GEMM_SMEM>>>(
        x, sgw, sg, T_TOK, ISH, H_DIM);
    gemm_mma<0><<<dim3(ISH/64, T_TOK/128, 1), 256, GEMM_SMEM>>>(
        x, suw, su, T_TOK, ISH, H_DIM);
    {
        size_t n = (size_t)T_TOK * ISH;
        silu_mul_shared_kernel<<<(unsigned)((n + 255)/256), 256>>>();
    }
    gemm_mma<0><<<dim3(H_DIM/64, T_TOK/128, 1), 256, GEMM_SMEM>>>(
        smid, sdw, out, T_TOK, H_DIM, ISH);

    // grouped experts: gu = gather(x)@gate_up^T  (N = 2I = 1024, K = H)
    gemm_mma<1><<<dim3(2*IDIM/64, CAP/128, NE), 256, GEMM_SMEM>>>(
        x, gup, gu, CAP, 2*IDIM, H_DIM);
    {
        size_t n = (size_t)NPAIR * IDIM;
        silu_mul_grouped_kernel<<<(unsigned)((n + 255)/256), 256>>>();
    }
    // y = hmid @ down^T  (N = H, K = I = 512)
    gemm_mma<2><<<dim3(H_DIM/64, CAP/128, NE), 256, GEMM_SMEM>>>(
        hmid, dwn, y, CAP, H_DIM, IDIM);

    // deterministic combine
    combine_kernel<<<dim3(T_TOK, H_DIM/256), 256>>>(out);

    (void)in_sizes; (void)n_in; (void)out_size;
}

// round 13
// speedup vs baseline: 1.1192x; 1.0036x over previous
#include <cuda_runtime.h>
#include <cstdint>
#include <math.h>

#define T_TOK 2048
#define H_DIM 1024
#define NE    32
#define IDIM  512
#define K_TOP 6
#define ISH   1024
#define CAP   2048
#define NPAIR (T_TOK*K_TOP)   // 12288

// ---------------- scratch (static device globals; no runtime alloc) ----------
__device__ int   g_counts[NE];
__device__ int   g_offsets[NE];
__device__ int   g_bucket[NE*CAP];
__device__ int   g_topidx[NPAIR];
__device__ float g_topw[NPAIR];
__device__ int   g_slot[NPAIR];
__device__ float g_sg  [(size_t)T_TOK*ISH];
__device__ float g_su  [(size_t)T_TOK*ISH];
__device__ float g_smid[(size_t)T_TOK*ISH];
__device__ float g_gu  [(size_t)NPAIR*2*IDIM];
__device__ float g_hmid[(size_t)NPAIR*IDIM];
__device__ float g_y   [(size_t)NPAIR*H_DIM];

__device__ __forceinline__ float silu_f(float v){ return v / (1.f + __expf(-v)); }

__device__ __forceinline__ uint32_t smem_u32(const void* p){
    uint32_t a;
    asm("{ .reg .u64 t; cvta.to.shared.u64 t, %1; cvt.u32.u64 %0, t; }"
        : "=r"(a) : "l"(p));
    return a;
}

__device__ __forceinline__ void cpa16(uint32_t dst, const void* src, bool valid){
    asm volatile("cp.async.cg.shared.global [%0], [%1], 16, %2;"
                 :: "r"(dst), "l"(src), "r"(valid ? 16u : 0u) : "memory");
}
#define CPA_COMMIT() asm volatile("cp.async.commit_group;" ::: "memory")
#define CPA_WAIT1()  asm volatile("cp.async.wait_group 1;" ::: "memory")
#define CPA_WAIT0()  asm volatile("cp.async.wait_group 0;" ::: "memory")

// bf16 m16n8k16 mma, fp32 accumulate
__device__ __forceinline__ void mma16(float* c, const uint32_t* a, const uint32_t* b){
    asm volatile("mma.sync.aligned.m16n8k16.row.col.f32.bf16.bf16.f32 "
                 "{%0,%1,%2,%3}, {%4,%5,%6,%7}, {%8,%9}, {%0,%1,%2,%3};"
                 : "+f"(c[0]), "+f"(c[1]), "+f"(c[2]), "+f"(c[3])
                 : "r"(a[0]), "r"(a[1]), "r"(a[2]), "r"(a[3]),
                   "r"(b[0]), "r"(b[1]));
}

// split a float2 (consecutive k) into bf16x2 hi + bf16x2 lo (low half = first k)
__device__ __forceinline__ void split2(float2 f, uint32_t& hi, uint32_t& lo){
    asm("cvt.rn.bf16x2.f32 %0, %1, %2;" : "=r"(hi) : "f"(f.y), "f"(f.x));
    float h0 = __uint_as_float(hi << 16);
    float h1 = __uint_as_float(hi & 0xFFFF0000u);
    float l0 = f.x - h0, l1 = f.y - h1;
    asm("cvt.rn.bf16x2.f32 %0, %1, %2;" : "=r"(lo) : "f"(l1), "f"(l0));
}

// swizzled float2 load from a 32-float-wide smem tile
// store-side swizzle: col4 ^= (row&3)<<1 (16B units) => float col ^= (row&3)<<3
__device__ __forceinline__ float2 lds2(const float* base, int row, int col){
    int idx = row*32 + (col ^ ((row & 3) << 3));
    return *(const float2*)(base + idx);
}

// ======================= 3xBF16 mma.sync GEMM (128x64 tile) ==================
// C[m,n] = sum_k A[m,k] * B[n,k]   (A, B both K-contiguous, fp32)
// CTA tile 128x64, BK=32, 256 threads = 8 warps (4m x 2n), warp tile 32x32.
// acc = 32 regs/thread -> __launch_bounds__(256,2) = 2 CTAs/SM.
// fp32 tiles in smem via cp.async (double-buffered); fragments split into
// bf16 hi/lo in registers; D = Ahi*Bhi + Ahi*Blo + Alo*Bhi (fp32 accum).
// smem: A0 16K | A1 16K | B0 8K | B1 8K = 48KB.
// MODE 0: dense; MODE 1: grouped gather via g_bucket; MODE 2: grouped compact.

#define GEMM_SMEM 49152

template<int MODE>
__global__ __launch_bounds__(256, 2)
void gemm_mma(const float* __restrict__ A, const float* __restrict__ W,
              float* __restrict__ C, int M, int N, int K)
{
    int e = 0, cnt = M, off = 0;
    const float* Wp = W;
    if (MODE){
        e = blockIdx.z;
        cnt = g_counts[e];
        if ((int)blockIdx.y * 128 >= cnt) return;
        off = g_offsets[e];
        Wp += (size_t)e * N * K;
    }
    const int m0 = blockIdx.y * 128, n0 = blockIdx.x * 64;

    extern __shared__ float smf[];   // A0[4096] A1[4096] B0[2048] B1[2048]
    const uint32_t sb = smem_u32(smf);

    const int tid = threadIdx.x, warp = tid >> 5, lane = tid & 31;
    const int wm = (warp & 3) * 32, wn = (warp >> 2) * 32;
    const int r4 = lane >> 2, c2 = lane & 3;

    // global load setup: A 4 rows/thread, B 2 rows/thread
    const int lr0 = tid >> 3, c4 = tid & 7;
    const float* ap[4]; bool av[4]; uint32_t soA[4];
    #pragma unroll
    for (int j = 0; j < 4; j++){
        int r = lr0 + j*32;
        soA[j] = (uint32_t)(r*128 + ((c4 ^ ((r & 3) << 1)) << 4));
        int m = m0 + r;
        size_t garow;
        if (MODE == 0){ av[j] = true; garow = (size_t)m; }
        else if (MODE == 1){ av[j] = m < cnt; garow = av[j] ? (size_t)g_bucket[e*CAP + m] : 0; }
        else { av[j] = m < cnt; garow = (size_t)(off + (av[j] ? m : 0)); }
        ap[j] = A + garow * (size_t)K + c4*4;
    }
    const float* bp[2]; uint32_t soB[2];
    #pragma unroll
    for (int j = 0; j < 2; j++){
        int r = lr0 + j*32;                      // 0..63
        soB[j] = (uint32_t)(r*128 + ((c4 ^ ((r & 3) << 1)) << 4));
        bp[j] = Wp + (size_t)(n0 + r) * K + c4*4;
    }

    float acc[2][4][4];
    #pragma unroll
    for (int a = 0; a < 2; a++)
    #pragma unroll
    for (int b = 0; b < 4; b++)
    #pragma unroll
    for (int q = 0; q < 4; q++) acc[a][b][q] = 0.f;

    const int nk = K >> 5;

    // prologue: chunk 0 -> buf 0   (A at 0, B at float offset 8192)
    #pragma unroll
    for (int j = 0; j < 4; j++) cpa16(sb + soA[j], ap[j], av[j]);
    #pragma unroll
    for (int j = 0; j < 2; j++) cpa16(sb + 32768 + soB[j], bp[j], true);
    CPA_COMMIT();

    for (int ch = 0; ch < nk; ch++){
        const int b = ch & 1;
        if (ch + 1 < nk){
            const int nb = (ch + 1) & 1;
            const int ko = (ch + 1) << 5;
            #pragma unroll
            for (int j = 0; j < 4; j++)
                cpa16(sb + (uint32_t)(nb*16384) + soA[j], ap[j] + ko, av[j]);
            #pragma unroll
            for (int j = 0; j < 2; j++)
                cpa16(sb + 32768 + (uint32_t)(nb*8192) + soB[j], bp[j] + ko, true);
            CPA_COMMIT();
            CPA_WAIT1();
        } else {
            CPA_WAIT0();
        }
        __syncthreads();

        const float* Ab = smf + b * 4096;
        const float* Bb = smf + 8192 + b * 2048;

        #pragma unroll
        for (int ks = 0; ks < 2; ks++){
            const int kb = ks * 16 + 2*c2;
            // B fragments for 4 n-tiles (warp covers 32 n), split hi/lo
            uint32_t bhi[4][2], blo[4][2];
            #pragma unroll
            for (int nf = 0; nf < 4; nf++){
                const int nr = wn + nf*8 + r4;
                split2(lds2(Bb, nr, kb),     bhi[nf][0], blo[nf][0]);
                split2(lds2(Bb, nr, kb + 8), bhi[nf][1], blo[nf][1]);
            }
            #pragma unroll
            for (int mf = 0; mf < 2; mf++){
                const int mr = wm + mf*16 + r4;
                uint32_t ahi[4], alo[4];
                split2(lds2(Ab, mr,     kb),     ahi[0], alo[0]);
                split2(lds2(Ab, mr + 8, kb),     ahi[1], alo[1]);
                split2(lds2(Ab, mr,     kb + 8), ahi[2], alo[2]);
                split2(lds2(Ab, mr + 8, kb + 8), ahi[3], alo[3]);
                #pragma unroll
                for (int nf = 0; nf < 4; nf++){
                    mma16(acc[mf][nf], ahi, bhi[nf]);
                    mma16(acc[mf][nf], ahi, blo[nf]);
                    mma16(acc[mf][nf], alo, bhi[nf]);
                }
            }
        }
        __syncthreads();
    }

    // epilogue: c0,c1 at (row, col..col+1); c2,c3 at (row+8, col..col+1)
    #pragma unroll
    for (int mf = 0; mf < 2; mf++){
        const int rl = wm + mf*16 + r4;
        #pragma unroll
        for (int half = 0; half < 2; half++){
            const int rloc = rl + half*8;
            bool valid; size_t crow;
            if (MODE == 0){ valid = (m0 + rloc) < M; crow = (size_t)(m0 + rloc); }
            else { valid = rloc < (cnt - m0); crow = (size_t)(off + m0 + rloc); }
            if (valid){
                float* cp = C + crow * N + n0 + wn + c2*2;
                #pragma unroll
                for (int nf = 0; nf < 4; nf++){
                    float2 v;
                    v.x = acc[mf][nf][half*2 + 0];
                    v.y = acc[mf][nf][half*2 + 1];
                    *(float2*)(cp + nf*8) = v;
                }
            }
        }
    }
}

// ---------------- router: softmax + bias + top-6 + bucketing ----------------
__global__ void zero_counts_kernel(){
    if (threadIdx.x < NE) g_counts[threadIdx.x] = 0;
}

__global__ void router_kernel(const float* __restrict__ x,
                              const float* __restrict__ rw,
                              const float* __restrict__ bias)
{
    __shared__ float sx[H_DIM];
    __shared__ float slog[NE];
    const int t = blockIdx.x;
    const float* xr = x + (size_t)t * H_DIM;
    for (int i = threadIdx.x; i < H_DIM; i += blockDim.x) sx[i] = xr[i];
    __syncthreads();

    const int warp = threadIdx.x >> 5, lane = threadIdx.x & 31;
    for (int e = warp*8; e < warp*8 + 8; e++){
        const float* w = rw + (size_t)e * H_DIM;
        float s = 0.f;
        for (int h = lane; h < H_DIM; h += 32) s += sx[h] * w[h];
        #pragma unroll
        for (int o = 16; o; o >>= 1) s += __shfl_xor_sync(0xffffffffu, s, o);
        if (lane == 0) slog[e] = s;
    }
    __syncthreads();

    if (threadIdx.x == 0){
        float mx = -1e30f;
        for (int e = 0; e < NE; e++) mx = fmaxf(mx, slog[e]);
        float p[NE]; float sum = 0.f;
        for (int e = 0; e < NE; e++){ p[e] = expf(slog[e] - mx); sum += p[e]; }
        float inv = 1.f / sum;
        float corr[NE];
        for (int e = 0; e < NE; e++){ p[e] *= inv; corr[e] = p[e] + bias[e]; }

        int idx[K_TOP]; bool used[NE];
        for (int e = 0; e < NE; e++) used[e] = false;
        for (int k = 0; k < K_TOP; k++){
            int best = -1; float bv = -1e30f;
            for (int e = 0; e < NE; e++)
                if (!used[e] && corr[e] > bv){ bv = corr[e]; best = e; }
            used[best] = true; idx[k] = best;
        }
        float wsum = 0.f;
        for (int k = 0; k < K_TOP; k++) wsum += p[idx[k]];
        wsum = fmaxf(wsum, 1e-12f);
        for (int k = 0; k < K_TOP; k++){
            int e = idx[k];
            float wn = p[e] / wsum;
            int slot = atomicAdd(&g_counts[e], 1);
            g_bucket[e*CAP + slot] = t;
            g_topidx[t*K_TOP + k] = e;
            g_topw [t*K_TOP + k] = wn;
            g_slot [t*K_TOP + k] = slot;
        }
    }
}

__global__ void scan_kernel(){
    if (threadIdx.x == 0){
        int s = 0;
        for (int e = 0; e < NE; e++){ g_offsets[e] = s; s += g_counts[e]; }
    }
}

// ---------------- elementwise -------------------------------------------------
__global__ void silu_mul_shared_kernel(){
    size_t i = (size_t)blockIdx.x * blockDim.x + threadIdx.x;
    if (i < (size_t)T_TOK * ISH)
        g_smid[i] = silu_f(g_sg[i]) * g_su[i];
}

__global__ void silu_mul_grouped_kernel(){
    size_t i = (size_t)blockIdx.x * blockDim.x + threadIdx.x;
    if (i < (size_t)NPAIR * IDIM){
        size_t p = i / IDIM, c = i % IDIM;
        g_hmid[i] = silu_f(g_gu[p*2*IDIM + c]) * g_gu[p*2*IDIM + IDIM + c];
    }
}

// ---------------- combine: deterministic per-token sum of 6 expert rows ------
__global__ void combine_kernel(float* __restrict__ out){
    const int t = blockIdx.x;
    const int h = blockIdx.y * 256 + threadIdx.x;
    float acc = 0.f;
    #pragma unroll
    for (int k = 0; k < K_TOP; k++){
        int e    = g_topidx[t*K_TOP + k];
        float w  = g_topw [t*K_TOP + k];
        int row  = g_offsets[e] + g_slot[t*K_TOP + k];
        acc += w * g_y[(size_t)row * H_DIM + h];
    }
    out[(size_t)t * H_DIM + h] += acc;   // out already holds shared_out
}

// ---------------- launch ------------------------------------------------------
static void* sym(const void* s){ void* p; cudaGetSymbolAddress(&p, s); return p; }

extern "C" void kernel_launch(void* const* d_in, const int* in_sizes, int n_in,
                              void* d_out, int out_size)
{
    const float* x    = (const float*)d_in[0];
    const float* rw   = (const float*)d_in[1];
    const float* bias = (const float*)d_in[2];
    const float* gup  = (const float*)d_in[3];
    const float* dwn  = (const float*)d_in[4];
    const float* sgw  = (const float*)d_in[5];
    const float* suw  = (const float*)d_in[6];
    const float* sdw  = (const float*)d_in[7];
    float* out = (float*)d_out;

    float *sg = (float*)sym(g_sg), *su = (float*)sym(g_su);
    float *smid = (float*)sym(g_smid);
    float *gu = (float*)sym(g_gu), *hmid = (float*)sym(g_hmid);
    float *y = (float*)sym(g_y);

    cudaFuncSetAttribute(gemm_mma<0>, cudaFuncAttributeMaxDynamicSharedMemorySize, GEMM_SMEM);
    cudaFuncSetAttribute(gemm_mma<1>, cudaFuncAttributeMaxDynamicSharedMemorySize, GEMM_SMEM);
    cudaFuncSetAttribute(gemm_mma<2>, cudaFuncAttributeMaxDynamicSharedMemorySize, GEMM_SMEM);

    // routing
    zero_counts_kernel<<<1, 32>>>();
    router_kernel<<<T_TOK, 128>>>(x, rw, bias);
    scan_kernel<<<1, 32>>>();

    // shared expert: sg = x@Wg^T, su = x@Wu^T, smid = silu(sg)*su, out = smid@Wd^T
    gemm_mma<0><<<dim3(ISH/64, T_TOK/128, 1), 256, GEMM_SMEM>>>(
        x, sgw, sg, T_TOK, ISH, H_DIM);
    gemm_mma<0><<<dim3(ISH/64, T_TOK/128, 1), 256, GEMM_SMEM>>>(
        x, suw, su, T_TOK, ISH, H_DIM);
    {
        size_t n = (size_t)T_TOK * ISH;
        silu_mul_shared_kernel<<<(unsigned)((n + 255)/256), 256>>>();
    }
    gemm_mma<0><<<dim3(H_DIM/64, T_TOK/128, 1), 256, GEMM_SMEM>>>(
        smid, sdw, out, T_TOK, H_DIM, ISH);

    // grouped experts: gu = gather(x)@gate_up^T  (N = 2I = 1024, K = H)
    gemm_mma<1><<<dim3(2*IDIM/64, CAP/128, NE), 256, GEMM_SMEM>>>(
        x, gup, gu, CAP, 2*IDIM, H_DIM);
    {
        size_t n = (size_t)NPAIR * IDIM;
        silu_mul_grouped_kernel<<<(unsigned)((n + 255)/256), 256>>>();
    }
    // y = hmid @ down^T  (N = H, K = I = 512)
    gemm_mma<2><<<dim3(H_DIM/64, CAP/128, NE), 256, GEMM_SMEM>>>(
        hmid, dwn, y, CAP, H_DIM, IDIM);

    // deterministic combine
    combine_kernel<<<dim3(T_TOK, H_DIM/256), 256>>>(out);

    (void)in_sizes; (void)n_in; (void)out_size;
}